// round 9
// baseline (speedup 1.0000x reference)
#include <cuda_runtime.h>
#include <cuda_bf16.h>
#include <stdint.h>

#define N_NODES 100000
#define N_EDGES 1600000
#define IN_DIM  128
#define HID_DIM 64
#define OUT_DIM 128

// Scratch (allocation-free rule: __device__ globals)
__device__ __align__(16) float g_hs [(size_t)N_NODES * HID_DIM];   // (x@Wc)*dinv[row]
__device__ int g_cnt[N_NODES];
__device__ int g_off[N_NODES];   // global exclusive scan of cnt
__device__ int g_pos[N_NODES];
__device__ int g_bpub[128];      // packed (sum | FLAG) per scan block
__device__ int g_csr[N_EDGES];

#define PUB_FLAG 0x40000000

// ---------------------------------------------------------------- f32x2 helpers
__device__ __forceinline__ unsigned long long pack2(float x, float y) {
    unsigned long long r;
    asm("mov.b64 %0, {%1,%2};" : "=l"(r) : "f"(x), "f"(y));
    return r;
}
__device__ __forceinline__ float2 unpack2(unsigned long long v) {
    float2 r;
    asm("mov.b64 {%0,%1}, %2;" : "=f"(r.x), "=f"(r.y) : "l"(v));
    return r;
}
__device__ __forceinline__ void ffma2(unsigned long long& d, unsigned long long a,
                                      unsigned long long b) {
    asm("fma.rn.f32x2 %0, %1, %2, %0;" : "+l"(d) : "l"(a), "l"(b));
}
__device__ __forceinline__ unsigned long long mul2(unsigned long long a,
                                                   unsigned long long b) {
    unsigned long long d;
    asm("mul.rn.f32x2 %0, %1, %2;" : "=l"(d) : "l"(a), "l"(b));
    return d;
}
__device__ __forceinline__ unsigned long long add2(unsigned long long a,
                                                   unsigned long long b) {
    unsigned long long d;
    asm("add.rn.f32x2 %0, %1, %2;" : "=l"(d) : "l"(a), "l"(b));
    return d;
}

// ---------------------------------------------------------------- cp.async
__device__ __forceinline__ void cpa16(uint32_t dst, const void* src) {
    asm volatile("cp.async.cg.shared.global [%0], [%1], 16;" :: "r"(dst), "l"(src));
}
#define CPA_COMMIT() asm volatile("cp.async.commit_group;")
#define CPA_WAIT(N)  asm volatile("cp.async.wait_group %0;" :: "n"(N))

// ---------------------------------------------------------------- CSR build
__global__ void zero_kernel(int n) {
    int i = blockIdx.x * blockDim.x + threadIdx.x;
    if (i < n) g_cnt[i] = 0;
    if (i < 128) g_bpub[i] = 0;
}

// 4 edges per thread (int4)
__global__ void cnt_kernel(const int4* __restrict__ dst4, int e) {
    int i = blockIdx.x * blockDim.x + threadIdx.x;
    int e4 = e >> 2;
    if (i < e4) {
        int4 d = dst4[i];
        atomicAdd(&g_cnt[d.x], 1);
        atomicAdd(&g_cnt[d.y], 1);
        atomicAdd(&g_cnt[d.z], 1);
        atomicAdd(&g_cnt[d.w], 1);
    }
    if (i == 0) {
        const int* d1 = (const int*)dst4;
        for (int j = e4 * 4; j < e; j++) atomicAdd(&g_cnt[d1[j]], 1);
    }
}

// Single-pass exclusive scan (decoupled lookback; all blocks co-resident).
__global__ __launch_bounds__(1024) void scan_kernel(int n) {
    __shared__ int sh[1024];
    __shared__ int red[1024];
    const int t = threadIdx.x;
    const int b = blockIdx.x;
    const int i = b * 1024 + t;
    int v = (i < n) ? g_cnt[i] : 0;
    sh[t] = v;
    __syncthreads();
    #pragma unroll
    for (int d = 1; d < 1024; d <<= 1) {
        int u = (t >= d) ? sh[t - d] : 0;
        __syncthreads();
        sh[t] += u;
        __syncthreads();
    }
    int incl = sh[t];
    if (t == 1023) atomicExch(&g_bpub[b], incl | PUB_FLAG);

    int pv = 0;
    if (t < b) {
        int w;
        do { w = atomicAdd(&g_bpub[t], 0); } while ((w & PUB_FLAG) == 0);
        pv = w & (PUB_FLAG - 1);
    }
    red[t] = pv;
    __syncthreads();
    #pragma unroll
    for (int s = 512; s > 0; s >>= 1) {
        if (t < s) red[t] += red[t + s];
        __syncthreads();
    }
    int prefix = red[0];
    if (i < n) { g_off[i] = prefix + incl - v; g_pos[i] = 0; }
}

// ---------------------------------------------------------------- GEMM1 + fill
// Blocks [0, nGemm): hs[r][c] = rsqrt(cnt[r]+1) * sum_k x[r][k]*Wc[k][c]
//   M=128 tile, N=64, K in 4 chunks of 32, double-buffered cp.async pipeline.
// Blocks [nGemm, ...): CSR fill, 4 edges/thread (overlaps with the GEMM).
// Dynamic smem: Xs[2][128*9] float4 (36 KB) + Ws[2][512] float4 (16 KB) = 52 KB.
__global__ __launch_bounds__(256, 3) void gemm1_fill_kernel(const float* __restrict__ x,
                                                            const float* __restrict__ Wc,
                                                            const int* __restrict__ src,
                                                            const int* __restrict__ dst,
                                                            int n, int e, int nGemm) {
    extern __shared__ float4 smem[];
    float4* Xs = smem;                 // [2][128*9]
    float4* Ws = smem + 2 * 128 * 9;   // [2][512]

    if (blockIdx.x >= nGemm) {   // ---- fill part (no smem use)
        int i = (blockIdx.x - nGemm) * 256 + threadIdx.x;
        int e4 = e >> 2;
        if (i < e4) {
            int4 s4 = ((const int4*)src)[i];
            int4 d4 = ((const int4*)dst)[i];
            int p;
            p = g_off[d4.x] + atomicAdd(&g_pos[d4.x], 1); g_csr[p] = s4.x;
            p = g_off[d4.y] + atomicAdd(&g_pos[d4.y], 1); g_csr[p] = s4.y;
            p = g_off[d4.z] + atomicAdd(&g_pos[d4.z], 1); g_csr[p] = s4.z;
            p = g_off[d4.w] + atomicAdd(&g_pos[d4.w], 1); g_csr[p] = s4.w;
        }
        if (i == 0) {
            for (int j = e4 * 4; j < e; j++) {
                int d = dst[j];
                int p = g_off[d] + atomicAdd(&g_pos[d], 1);
                g_csr[p] = src[j];
            }
        }
        return;
    }

    const int t = threadIdx.x;
    const int rowBase = blockIdx.x * 128;
    const int tr = t & 31;
    const int tc = t >> 5;

    const float4* Xg = (const float4*)x;
    const float4* Wg = (const float4*)Wc;

    // per-thread source precompute for the pipeline loads
    // W: 2 elems/thread; X: 4 elems/thread (row clamped: garbage rows never stored)
    int wIdx0 = t, wIdx1 = t + 256;
    int xr[4], xq[4];
    const float4* xsrc[4];
    #pragma unroll
    for (int i = 0; i < 4; i++) {
        int idx = t + i * 256;
        xr[i] = idx >> 3; xq[i] = idx & 7;
        int row = rowBase + xr[i];
        if (row >= n) row = n - 1;
        xsrc[i] = Xg + (size_t)row * 32 + xq[i];
    }
    uint32_t xdst[4], wdst0, wdst1;
    #pragma unroll
    for (int i = 0; i < 4; i++)
        xdst[i] = (uint32_t)__cvta_generic_to_shared(&Xs[xr[i] * 9 + xq[i]]);
    wdst0 = (uint32_t)__cvta_generic_to_shared(&Ws[wIdx0]);
    wdst1 = (uint32_t)__cvta_generic_to_shared(&Ws[wIdx1]);
    const uint32_t XBUF = 128 * 9 * 16;   // bytes per X buffer
    const uint32_t WBUF = 512 * 16;       // bytes per W buffer

    unsigned long long acc[4][4];
    #pragma unroll
    for (int i = 0; i < 4; i++)
        #pragma unroll
        for (int c2 = 0; c2 < 4; c2++) acc[i][c2] = 0ull;

    // prologue: stage chunk 0 into buffer 0
    {
        cpa16(wdst0, Wg + ((0 * 32 + (wIdx0 >> 4)) * 16 + (wIdx0 & 15)));
        cpa16(wdst1, Wg + ((0 * 32 + (wIdx1 >> 4)) * 16 + (wIdx1 & 15)));
        #pragma unroll
        for (int i = 0; i < 4; i++) cpa16(xdst[i], xsrc[i] + 0 * 8);
        CPA_COMMIT();
    }

    #pragma unroll
    for (int c = 0; c < 4; c++) {
        const int nb = c & 1;
        if (c < 3) {   // prefetch next chunk into other buffer
            const int ob = nb ^ 1;
            cpa16(wdst0 + ob * WBUF, Wg + (((c + 1) * 32 + (wIdx0 >> 4)) * 16 + (wIdx0 & 15)));
            cpa16(wdst1 + ob * WBUF, Wg + (((c + 1) * 32 + (wIdx1 >> 4)) * 16 + (wIdx1 & 15)));
            #pragma unroll
            for (int i = 0; i < 4; i++) cpa16(xdst[i] + ob * XBUF, xsrc[i] + (c + 1) * 8);
            CPA_COMMIT();
            CPA_WAIT(1);
        } else {
            CPA_WAIT(0);
        }
        __syncthreads();

        const float4* Xb = Xs + nb * 128 * 9;
        const float4* Wb = Ws + nb * 512;
        #pragma unroll
        for (int kq = 0; kq < 8; kq++) {
            float4 xv[4];
            #pragma unroll
            for (int i = 0; i < 4; i++) xv[i] = Xb[(tr + 32 * i) * 9 + kq];
            #pragma unroll
            for (int kk = 0; kk < 4; kk++) {
                float4 w0 = Wb[(kq * 4 + kk) * 16 + tc * 2];
                float4 w1 = Wb[(kq * 4 + kk) * 16 + tc * 2 + 1];
                unsigned long long wp0 = pack2(w0.x, w0.y);
                unsigned long long wp1 = pack2(w0.z, w0.w);
                unsigned long long wp2 = pack2(w1.x, w1.y);
                unsigned long long wp3 = pack2(w1.z, w1.w);
                #pragma unroll
                for (int i = 0; i < 4; i++) {
                    float s = (kk == 0) ? xv[i].x : (kk == 1) ? xv[i].y
                            : (kk == 2) ? xv[i].z : xv[i].w;
                    unsigned long long ss = pack2(s, s);
                    ffma2(acc[i][0], ss, wp0);
                    ffma2(acc[i][1], ss, wp1);
                    ffma2(acc[i][2], ss, wp2);
                    ffma2(acc[i][3], ss, wp3);
                }
            }
        }
        __syncthreads();
    }

    #pragma unroll
    for (int i = 0; i < 4; i++) {
        int row = rowBase + tr + 32 * i;
        if (row < n) {
            float dv = rsqrtf((float)g_cnt[row] + 1.0f);
            unsigned long long dd = pack2(dv, dv);
            float2 a = unpack2(mul2(acc[i][0], dd));
            float2 b = unpack2(mul2(acc[i][1], dd));
            float2 cc = unpack2(mul2(acc[i][2], dd));
            float2 d = unpack2(mul2(acc[i][3], dd));
            size_t off = (size_t)row * 16 + tc * 2;
            ((float4*)g_hs)[off]     = make_float4(a.x, a.y, b.x, b.y);
            ((float4*)g_hs)[off + 1] = make_float4(cc.x, cc.y, d.x, d.y);
        }
    }
}

// ---------------------------------------------------------------- agg + GEMM2
// Block handles 64 rows. Phase 1: 16 groups of 16 threads aggregate 4 nodes each
// (self + CSR neighbors), apply dinv/bias/relu, write Hs. Phase 2: out = Hs@Wlin+blin.
__global__ __launch_bounds__(256) void agg_gemm2_kernel(const float* __restrict__ Wlin,
                                                        const float* __restrict__ bconv,
                                                        const float* __restrict__ blin,
                                                        float* __restrict__ out,
                                                        int n) {
    __shared__ float4 Hs[64 * 17];   // 64 rows x 16 float4 (+1 pad)
    __shared__ float4 Ws[32 * 32];   // 32 k x 128 cols
    const int t = threadIdx.x;
    const int rowBase = blockIdx.x * 64;
    const int tr = t & 31;
    const int tc = t >> 5;

    // ---- phase 1: aggregate
    {
        const int grp = t >> 4;      // 0..15
        const int c = t & 15;        // float4 chunk
        const float4* hs4 = (const float4*)g_hs;
        float4 bcv = __ldg((const float4*)&bconv[c * 4]);
        #pragma unroll
        for (int nn = 0; nn < 4; nn++) {
            int r = grp * 4 + nn;
            int node = rowBase + r;
            float4 res = make_float4(0.f, 0.f, 0.f, 0.f);
            if (node < n) {
                float4 a0 = hs4[(size_t)node * 16 + c];   // self-loop (pre-scaled)
                float4 a1 = make_float4(0.f, 0.f, 0.f, 0.f);
                float4 a2 = make_float4(0.f, 0.f, 0.f, 0.f);
                float4 a3 = make_float4(0.f, 0.f, 0.f, 0.f);
                int cnt = g_cnt[node];
                int beg = g_off[node];
                int end = beg + cnt;
                int j = beg;
                for (; j + 3 < end; j += 4) {
                    int s0 = g_csr[j],     s1 = g_csr[j + 1];
                    int s2 = g_csr[j + 2], s3 = g_csr[j + 3];
                    float4 v0 = hs4[(size_t)s0 * 16 + c];
                    float4 v1 = hs4[(size_t)s1 * 16 + c];
                    float4 v2 = hs4[(size_t)s2 * 16 + c];
                    float4 v3 = hs4[(size_t)s3 * 16 + c];
                    a0.x += v0.x; a0.y += v0.y; a0.z += v0.z; a0.w += v0.w;
                    a1.x += v1.x; a1.y += v1.y; a1.z += v1.z; a1.w += v1.w;
                    a2.x += v2.x; a2.y += v2.y; a2.z += v2.z; a2.w += v2.w;
                    a3.x += v3.x; a3.y += v3.y; a3.z += v3.z; a3.w += v3.w;
                }
                for (; j < end; j++) {
                    int s0 = g_csr[j];
                    float4 v0 = hs4[(size_t)s0 * 16 + c];
                    a0.x += v0.x; a0.y += v0.y; a0.z += v0.z; a0.w += v0.w;
                }
                a0.x += a1.x + a2.x + a3.x;
                a0.y += a1.y + a2.y + a3.y;
                a0.z += a1.z + a2.z + a3.z;
                a0.w += a1.w + a2.w + a3.w;
                float dv = rsqrtf((float)cnt + 1.0f);
                res.x = fmaxf(fmaf(a0.x, dv, bcv.x), 0.f);
                res.y = fmaxf(fmaf(a0.y, dv, bcv.y), 0.f);
                res.z = fmaxf(fmaf(a0.z, dv, bcv.z), 0.f);
                res.w = fmaxf(fmaf(a0.w, dv, bcv.w), 0.f);
            }
            Hs[r * 17 + c] = res;
        }
    }

    // ---- phase 2: GEMM, K=64 in 2 chunks of 32 (Ws reuse)
    unsigned long long acc[2][8];
    #pragma unroll
    for (int i = 0; i < 2; i++)
        #pragma unroll
        for (int c2 = 0; c2 < 8; c2++) acc[i][c2] = 0ull;

    const float4* Wg = (const float4*)Wlin;

    for (int c = 0; c < 2; c++) {
        __syncthreads();   // Hs ready (c==0) / Ws drained (c==1)
        #pragma unroll
        for (int i = 0; i < 4; i++) {
            int idx = t + i * 256;
            int k = idx >> 5, col4 = idx & 31;
            Ws[idx] = Wg[(c * 32 + k) * 32 + col4];
        }
        __syncthreads();

        #pragma unroll
        for (int kq = 0; kq < 8; kq++) {
            float4 xv[2];
            #pragma unroll
            for (int i = 0; i < 2; i++) xv[i] = Hs[(tr + 32 * i) * 17 + c * 8 + kq];
            #pragma unroll
            for (int kk = 0; kk < 4; kk++) {
                unsigned long long wp[8];
                #pragma unroll
                for (int m = 0; m < 4; m++) {
                    float4 w = Ws[(kq * 4 + kk) * 32 + tc * 4 + m];
                    wp[m * 2]     = pack2(w.x, w.y);
                    wp[m * 2 + 1] = pack2(w.z, w.w);
                }
                #pragma unroll
                for (int i = 0; i < 2; i++) {
                    float s = (kk == 0) ? xv[i].x : (kk == 1) ? xv[i].y
                            : (kk == 2) ? xv[i].z : xv[i].w;
                    unsigned long long ss = pack2(s, s);
                    #pragma unroll
                    for (int c2 = 0; c2 < 8; c2++) ffma2(acc[i][c2], ss, wp[c2]);
                }
            }
        }
    }

    unsigned long long blp[8];
    #pragma unroll
    for (int m = 0; m < 4; m++) {
        float4 b = __ldg((const float4*)&blin[tc * 16 + m * 4]);
        blp[m * 2]     = pack2(b.x, b.y);
        blp[m * 2 + 1] = pack2(b.z, b.w);
    }
    #pragma unroll
    for (int i = 0; i < 2; i++) {
        int row = rowBase + tr + 32 * i;
        if (row < n) {
            size_t off = (size_t)row * 32 + tc * 4;
            #pragma unroll
            for (int m = 0; m < 4; m++) {
                float2 lo = unpack2(add2(acc[i][m * 2],     blp[m * 2]));
                float2 hi = unpack2(add2(acc[i][m * 2 + 1], blp[m * 2 + 1]));
                ((float4*)out)[off + m] = make_float4(lo.x, lo.y, hi.x, hi.y);
            }
        }
    }
}

// ---------------------------------------------------------------- launch
extern "C" void kernel_launch(void* const* d_in, const int* in_sizes, int n_in,
                              void* d_out, int out_size) {
    const float* x  = (const float*)d_in[0];
    const int*   ei = (const int*)  d_in[1];
    const float* Wc = (const float*)d_in[2];
    const float* bc = (const float*)d_in[3];
    const float* Wl = (const float*)d_in[4];
    const float* bl = (const float*)d_in[5];
    float*       out = (float*)d_out;

    const int n = in_sizes[0] / IN_DIM;      // 100000
    const int e = in_sizes[1] / 2;           // 1600000
    const int* src = ei;
    const int* dst = ei + e;
    const int nb = (n + 1023) >> 10;         // 98 (must be <= 128)

    const int SMEM1 = (2 * 128 * 9 + 2 * 512) * 16;   // 53248 B
    cudaFuncSetAttribute(gemm1_fill_kernel,
                         cudaFuncAttributeMaxDynamicSharedMemorySize, SMEM1);

    zero_kernel<<<(n + 255) / 256, 256>>>(n);
    cnt_kernel <<<((e >> 2) + 255) / 256, 256>>>((const int4*)dst, e);
    scan_kernel<<<nb, 1024>>>(n);
    {
        int nGemm = (n + 127) / 128;
        int nFill = ((e >> 2) + 255) / 256;
        gemm1_fill_kernel<<<nGemm + nFill, 256, SMEM1>>>(x, Wc, src, dst, n, e, nGemm);
    }
    agg_gemm2_kernel<<<(n + 63) / 64, 256>>>(Wl, bc, bl, out, n);
}

// round 10
// speedup vs baseline: 1.5324x; 1.5324x over previous
#include <cuda_runtime.h>
#include <cuda_fp16.h>
#include <stdint.h>

#define N_NODES 100000
#define N_EDGES 1600000
#define IN_DIM  128
#define HID_DIM 64
#define OUT_DIM 128

// Scratch (allocation-free rule: __device__ globals)
__device__ __align__(16) __half g_hs[(size_t)N_NODES * HID_DIM];   // fp16 messages
__device__ int g_cnt[N_NODES];
__device__ int g_off[N_NODES];   // global exclusive scan of cnt
__device__ int g_pos[N_NODES];
__device__ int g_bpub[128];      // packed (sum | FLAG) per scan block
__device__ int g_csr[N_EDGES];

#define PUB_FLAG 0x40000000

// ---------------------------------------------------------------- f32x2 helpers
__device__ __forceinline__ unsigned long long pack2(float x, float y) {
    unsigned long long r;
    asm("mov.b64 %0, {%1,%2};" : "=l"(r) : "f"(x), "f"(y));
    return r;
}
__device__ __forceinline__ float2 unpack2(unsigned long long v) {
    float2 r;
    asm("mov.b64 {%0,%1}, %2;" : "=f"(r.x), "=f"(r.y) : "l"(v));
    return r;
}
__device__ __forceinline__ void ffma2(unsigned long long& d, unsigned long long a,
                                      unsigned long long b) {
    asm("fma.rn.f32x2 %0, %1, %2, %0;" : "+l"(d) : "l"(a), "l"(b));
}
__device__ __forceinline__ unsigned long long mul2(unsigned long long a,
                                                   unsigned long long b) {
    unsigned long long d;
    asm("mul.rn.f32x2 %0, %1, %2;" : "=l"(d) : "l"(a), "l"(b));
    return d;
}
__device__ __forceinline__ unsigned long long add2(unsigned long long a,
                                                   unsigned long long b) {
    unsigned long long d;
    asm("add.rn.f32x2 %0, %1, %2;" : "=l"(d) : "l"(a), "l"(b));
    return d;
}

// ---------------------------------------------------------------- CSR build
__global__ void zero_kernel(int n) {
    int i = blockIdx.x * blockDim.x + threadIdx.x;
    if (i < n) g_cnt[i] = 0;
    if (i < 128) g_bpub[i] = 0;
}

// 4 edges per thread (int4)
__global__ void cnt_kernel(const int4* __restrict__ dst4, int e) {
    int i = blockIdx.x * blockDim.x + threadIdx.x;
    int e4 = e >> 2;
    if (i < e4) {
        int4 d = dst4[i];
        atomicAdd(&g_cnt[d.x], 1);
        atomicAdd(&g_cnt[d.y], 1);
        atomicAdd(&g_cnt[d.z], 1);
        atomicAdd(&g_cnt[d.w], 1);
    }
    if (i == 0) {
        const int* d1 = (const int*)dst4;
        for (int j = e4 * 4; j < e; j++) atomicAdd(&g_cnt[d1[j]], 1);
    }
}

// Single-pass exclusive scan (decoupled lookback; all blocks co-resident).
__global__ __launch_bounds__(1024) void scan_kernel(int n) {
    __shared__ int sh[1024];
    __shared__ int red[1024];
    const int t = threadIdx.x;
    const int b = blockIdx.x;
    const int i = b * 1024 + t;
    int v = (i < n) ? g_cnt[i] : 0;
    sh[t] = v;
    __syncthreads();
    #pragma unroll
    for (int d = 1; d < 1024; d <<= 1) {
        int u = (t >= d) ? sh[t - d] : 0;
        __syncthreads();
        sh[t] += u;
        __syncthreads();
    }
    int incl = sh[t];
    if (t == 1023) atomicExch(&g_bpub[b], incl | PUB_FLAG);

    int pv = 0;
    if (t < b) {
        int w;
        do { w = atomicAdd(&g_bpub[t], 0); } while ((w & PUB_FLAG) == 0);
        pv = w & (PUB_FLAG - 1);
    }
    red[t] = pv;
    __syncthreads();
    #pragma unroll
    for (int s = 512; s > 0; s >>= 1) {
        if (t < s) red[t] += red[t + s];
        __syncthreads();
    }
    int prefix = red[0];
    if (i < n) { g_off[i] = prefix + incl - v; g_pos[i] = 0; }
}

// ---------------------------------------------------------------- GEMM1 + fill
// Blocks [0, nGemm): hs[r][c] = fp16( rsqrt(cnt[r]+1) * sum_k x[r][k]*Wc[k][c] )
//   Tile M=128, N=64, K chunks of 32 (R8 synchronous structure — known good).
// Blocks [nGemm, ...): CSR fill, 4 edges/thread (overlaps with the GEMM).
__global__ __launch_bounds__(256) void gemm1_fill_kernel(const float* __restrict__ x,
                                                         const float* __restrict__ Wc,
                                                         const int* __restrict__ src,
                                                         const int* __restrict__ dst,
                                                         int n, int e, int nGemm) {
    __shared__ float4 Xs[128 * 9];
    __shared__ float4 Ws[32 * 16];

    if (blockIdx.x >= nGemm) {   // ---- fill part
        int i = (blockIdx.x - nGemm) * 256 + threadIdx.x;
        int e4 = e >> 2;
        if (i < e4) {
            int4 s4 = ((const int4*)src)[i];
            int4 d4 = ((const int4*)dst)[i];
            int p;
            p = g_off[d4.x] + atomicAdd(&g_pos[d4.x], 1); g_csr[p] = s4.x;
            p = g_off[d4.y] + atomicAdd(&g_pos[d4.y], 1); g_csr[p] = s4.y;
            p = g_off[d4.z] + atomicAdd(&g_pos[d4.z], 1); g_csr[p] = s4.z;
            p = g_off[d4.w] + atomicAdd(&g_pos[d4.w], 1); g_csr[p] = s4.w;
        }
        if (i == 0) {
            for (int j = e4 * 4; j < e; j++) {
                int d = dst[j];
                int p = g_off[d] + atomicAdd(&g_pos[d], 1);
                g_csr[p] = src[j];
            }
        }
        return;
    }

    const int t = threadIdx.x;
    const int rowBase = blockIdx.x * 128;
    const int tr = t & 31;
    const int tc = t >> 5;

    unsigned long long acc[4][4];
    #pragma unroll
    for (int i = 0; i < 4; i++)
        #pragma unroll
        for (int c2 = 0; c2 < 4; c2++) acc[i][c2] = 0ull;

    const float4* Xg = (const float4*)x;
    const float4* Wg = (const float4*)Wc;

    for (int c = 0; c < 4; c++) {
        #pragma unroll
        for (int i = 0; i < 2; i++) {
            int idx = t + i * 256;
            int k = idx >> 4, col4 = idx & 15;
            Ws[idx] = Wg[(c * 32 + k) * 16 + col4];
        }
        #pragma unroll
        for (int i = 0; i < 4; i++) {
            int idx = t + i * 256;
            int r = idx >> 3, q = idx & 7;
            int row = rowBase + r;
            float4 v = make_float4(0.f, 0.f, 0.f, 0.f);
            if (row < n) v = Xg[(size_t)row * 32 + c * 8 + q];
            Xs[r * 9 + q] = v;
        }
        __syncthreads();

        #pragma unroll
        for (int kq = 0; kq < 8; kq++) {
            float4 xv[4];
            #pragma unroll
            for (int i = 0; i < 4; i++) xv[i] = Xs[(tr + 32 * i) * 9 + kq];
            #pragma unroll
            for (int kk = 0; kk < 4; kk++) {
                float4 w0 = Ws[(kq * 4 + kk) * 16 + tc * 2];
                float4 w1 = Ws[(kq * 4 + kk) * 16 + tc * 2 + 1];
                unsigned long long wp0 = pack2(w0.x, w0.y);
                unsigned long long wp1 = pack2(w0.z, w0.w);
                unsigned long long wp2 = pack2(w1.x, w1.y);
                unsigned long long wp3 = pack2(w1.z, w1.w);
                #pragma unroll
                for (int i = 0; i < 4; i++) {
                    float s = (kk == 0) ? xv[i].x : (kk == 1) ? xv[i].y
                            : (kk == 2) ? xv[i].z : xv[i].w;
                    unsigned long long ss = pack2(s, s);
                    ffma2(acc[i][0], ss, wp0);
                    ffma2(acc[i][1], ss, wp1);
                    ffma2(acc[i][2], ss, wp2);
                    ffma2(acc[i][3], ss, wp3);
                }
            }
        }
        __syncthreads();
    }

    #pragma unroll
    for (int i = 0; i < 4; i++) {
        int row = rowBase + tr + 32 * i;
        if (row < n) {
            float dv = rsqrtf((float)g_cnt[row] + 1.0f);
            unsigned long long dd = pack2(dv, dv);
            float2 a = unpack2(mul2(acc[i][0], dd));
            float2 b = unpack2(mul2(acc[i][1], dd));
            float2 cc = unpack2(mul2(acc[i][2], dd));
            float2 d = unpack2(mul2(acc[i][3], dd));
            __half2 h0 = __floats2half2_rn(a.x, a.y);
            __half2 h1 = __floats2half2_rn(b.x, b.y);
            __half2 h2 = __floats2half2_rn(cc.x, cc.y);
            __half2 h3 = __floats2half2_rn(d.x, d.y);
            uint4 pk;
            pk.x = *(unsigned int*)&h0;
            pk.y = *(unsigned int*)&h1;
            pk.z = *(unsigned int*)&h2;
            pk.w = *(unsigned int*)&h3;
            // row stride = 64 halves = 8 uint4; this thread owns chunk tc
            ((uint4*)g_hs)[(size_t)row * 8 + tc] = pk;
        }
    }
}

// ---------------------------------------------------------------- agg + GEMM2
// Block handles 64 rows. Phase 1: 8 threads/node (uint4 = 8 halves each),
// 32 nodes per pass, 2 passes; fp32 accumulate; dinv/bias/relu -> Hs.
// Phase 2: out = Hs@Wlin + blin (f32x2).
__global__ __launch_bounds__(256) void agg_gemm2_kernel(const float* __restrict__ Wlin,
                                                        const float* __restrict__ bconv,
                                                        const float* __restrict__ blin,
                                                        float* __restrict__ out,
                                                        int n) {
    __shared__ float4 Hs[64 * 17];   // 64 rows x 16 float4 (+1 pad)
    __shared__ float4 Ws[32 * 32];   // 32 k x 128 cols
    const int t = threadIdx.x;
    const int rowBase = blockIdx.x * 64;
    const int tr = t & 31;
    const int tc = t >> 5;

    // ---- phase 1: aggregate (fp16 gather, fp32 accumulate)
    {
        const int grp = t >> 3;      // 0..31 (node within pass)
        const int c8 = t & 7;        // uint4 chunk: floats [c8*8, c8*8+8)
        const uint4* hs4 = (const uint4*)g_hs;
        float4 bcv0 = __ldg((const float4*)&bconv[c8 * 8]);
        float4 bcv1 = __ldg((const float4*)&bconv[c8 * 8 + 4]);
        #pragma unroll
        for (int pass = 0; pass < 2; pass++) {
            int r = pass * 32 + grp;
            int node = rowBase + r;
            float4 r0 = make_float4(0.f, 0.f, 0.f, 0.f);
            float4 r1 = make_float4(0.f, 0.f, 0.f, 0.f);
            if (node < n) {
                float a[8] = {0,0,0,0,0,0,0,0};
                float b[8] = {0,0,0,0,0,0,0,0};
                // self-loop
                {
                    uint4 v = hs4[(size_t)node * 8 + c8];
                    const __half2* hp = (const __half2*)&v;
                    #pragma unroll
                    for (int m = 0; m < 4; m++) {
                        float2 f = __half22float2(hp[m]);
                        a[m * 2] += f.x; a[m * 2 + 1] += f.y;
                    }
                }
                int cnt = g_cnt[node];
                int beg = g_off[node];
                int end = beg + cnt;
                int j = beg;
                for (; j + 1 < end; j += 2) {
                    int s0 = g_csr[j], s1 = g_csr[j + 1];
                    uint4 v0 = hs4[(size_t)s0 * 8 + c8];
                    uint4 v1 = hs4[(size_t)s1 * 8 + c8];
                    const __half2* h0 = (const __half2*)&v0;
                    const __half2* h1 = (const __half2*)&v1;
                    #pragma unroll
                    for (int m = 0; m < 4; m++) {
                        float2 f0 = __half22float2(h0[m]);
                        float2 f1 = __half22float2(h1[m]);
                        a[m * 2] += f0.x; a[m * 2 + 1] += f0.y;
                        b[m * 2] += f1.x; b[m * 2 + 1] += f1.y;
                    }
                }
                if (j < end) {
                    int s0 = g_csr[j];
                    uint4 v0 = hs4[(size_t)s0 * 8 + c8];
                    const __half2* h0 = (const __half2*)&v0;
                    #pragma unroll
                    for (int m = 0; m < 4; m++) {
                        float2 f0 = __half22float2(h0[m]);
                        a[m * 2] += f0.x; a[m * 2 + 1] += f0.y;
                    }
                }
                float dv = rsqrtf((float)cnt + 1.0f);
                r0.x = fmaxf(fmaf(a[0] + b[0], dv, bcv0.x), 0.f);
                r0.y = fmaxf(fmaf(a[1] + b[1], dv, bcv0.y), 0.f);
                r0.z = fmaxf(fmaf(a[2] + b[2], dv, bcv0.z), 0.f);
                r0.w = fmaxf(fmaf(a[3] + b[3], dv, bcv0.w), 0.f);
                r1.x = fmaxf(fmaf(a[4] + b[4], dv, bcv1.x), 0.f);
                r1.y = fmaxf(fmaf(a[5] + b[5], dv, bcv1.y), 0.f);
                r1.z = fmaxf(fmaf(a[6] + b[6], dv, bcv1.z), 0.f);
                r1.w = fmaxf(fmaf(a[7] + b[7], dv, bcv1.w), 0.f);
            }
            Hs[r * 17 + c8 * 2]     = r0;
            Hs[r * 17 + c8 * 2 + 1] = r1;
        }
    }

    // ---- phase 2: GEMM, K=64 in 2 chunks of 32 (Ws reuse)
    unsigned long long acc[2][8];
    #pragma unroll
    for (int i = 0; i < 2; i++)
        #pragma unroll
        for (int c2 = 0; c2 < 8; c2++) acc[i][c2] = 0ull;

    const float4* Wg = (const float4*)Wlin;

    for (int c = 0; c < 2; c++) {
        __syncthreads();   // Hs ready (c==0) / Ws drained (c==1)
        #pragma unroll
        for (int i = 0; i < 4; i++) {
            int idx = t + i * 256;
            int k = idx >> 5, col4 = idx & 31;
            Ws[idx] = Wg[(c * 32 + k) * 32 + col4];
        }
        __syncthreads();

        #pragma unroll
        for (int kq = 0; kq < 8; kq++) {
            float4 xv[2];
            #pragma unroll
            for (int i = 0; i < 2; i++) xv[i] = Hs[(tr + 32 * i) * 17 + c * 8 + kq];
            #pragma unroll
            for (int kk = 0; kk < 4; kk++) {
                unsigned long long wp[8];
                #pragma unroll
                for (int m = 0; m < 4; m++) {
                    float4 w = Ws[(kq * 4 + kk) * 32 + tc * 4 + m];
                    wp[m * 2]     = pack2(w.x, w.y);
                    wp[m * 2 + 1] = pack2(w.z, w.w);
                }
                #pragma unroll
                for (int i = 0; i < 2; i++) {
                    float s = (kk == 0) ? xv[i].x : (kk == 1) ? xv[i].y
                            : (kk == 2) ? xv[i].z : xv[i].w;
                    unsigned long long ss = pack2(s, s);
                    #pragma unroll
                    for (int c2 = 0; c2 < 8; c2++) ffma2(acc[i][c2], ss, wp[c2]);
                }
            }
        }
    }

    unsigned long long blp[8];
    #pragma unroll
    for (int m = 0; m < 4; m++) {
        float4 b = __ldg((const float4*)&blin[tc * 16 + m * 4]);
        blp[m * 2]     = pack2(b.x, b.y);
        blp[m * 2 + 1] = pack2(b.z, b.w);
    }
    #pragma unroll
    for (int i = 0; i < 2; i++) {
        int row = rowBase + tr + 32 * i;
        if (row < n) {
            size_t off = (size_t)row * 32 + tc * 4;
            #pragma unroll
            for (int m = 0; m < 4; m++) {
                float2 lo = unpack2(add2(acc[i][m * 2],     blp[m * 2]));
                float2 hi = unpack2(add2(acc[i][m * 2 + 1], blp[m * 2 + 1]));
                ((float4*)out)[off + m] = make_float4(lo.x, lo.y, hi.x, hi.y);
            }
        }
    }
}

// ---------------------------------------------------------------- launch
extern "C" void kernel_launch(void* const* d_in, const int* in_sizes, int n_in,
                              void* d_out, int out_size) {
    const float* x  = (const float*)d_in[0];
    const int*   ei = (const int*)  d_in[1];
    const float* Wc = (const float*)d_in[2];
    const float* bc = (const float*)d_in[3];
    const float* Wl = (const float*)d_in[4];
    const float* bl = (const float*)d_in[5];
    float*       out = (float*)d_out;

    const int n = in_sizes[0] / IN_DIM;      // 100000
    const int e = in_sizes[1] / 2;           // 1600000
    const int* src = ei;
    const int* dst = ei + e;
    const int nb = (n + 1023) >> 10;         // 98 (must be <= 128)

    zero_kernel<<<(n + 255) / 256, 256>>>(n);
    cnt_kernel <<<((e >> 2) + 255) / 256, 256>>>((const int4*)dst, e);
    scan_kernel<<<nb, 1024>>>(n);
    {
        int nGemm = (n + 127) / 128;
        int nFill = ((e >> 2) + 255) / 256;
        gemm1_fill_kernel<<<nGemm + nFill, 256>>>(x, Wc, src, dst, n, e, nGemm);
    }
    agg_gemm2_kernel<<<(n + 63) / 64, 256>>>(Wl, bc, bl, out, n);
}

// round 11
// speedup vs baseline: 1.5393x; 1.0045x over previous
#include <cuda_runtime.h>
#include <cuda_fp16.h>
#include <stdint.h>

#define N_NODES 100000
#define N_EDGES 1600000
#define IN_DIM  128
#define HID_DIM 64
#define OUT_DIM 128

// Scratch (allocation-free rule: __device__ globals)
__device__ __align__(16) __half g_hs[(size_t)N_NODES * HID_DIM];   // fp16 messages
__device__ int g_cnt[N_NODES];
__device__ int g_off[N_NODES];   // global exclusive scan of cnt
__device__ int g_pos[N_NODES];
__device__ int g_bpub[128];      // packed (sum | FLAG) per scan block
__device__ int g_csr[N_EDGES];
__device__ int g_sync;           // zero_cnt grid handshake (reset by scan_kernel)
__device__ int g_sync_release;

#define PUB_FLAG 0x40000000

// ---------------------------------------------------------------- f32x2 helpers
__device__ __forceinline__ unsigned long long pack2(float x, float y) {
    unsigned long long r;
    asm("mov.b64 %0, {%1,%2};" : "=l"(r) : "f"(x), "f"(y));
    return r;
}
__device__ __forceinline__ float2 unpack2(unsigned long long v) {
    float2 r;
    asm("mov.b64 {%0,%1}, %2;" : "=f"(r.x), "=f"(r.y) : "l"(v));
    return r;
}
__device__ __forceinline__ void ffma2(unsigned long long& d, unsigned long long a,
                                      unsigned long long b) {
    asm("fma.rn.f32x2 %0, %1, %2, %0;" : "+l"(d) : "l"(a), "l"(b));
}
__device__ __forceinline__ unsigned long long mul2(unsigned long long a,
                                                   unsigned long long b) {
    unsigned long long d;
    asm("mul.rn.f32x2 %0, %1, %2;" : "=l"(d) : "l"(a), "l"(b));
    return d;
}
__device__ __forceinline__ unsigned long long add2(unsigned long long a,
                                                   unsigned long long b) {
    unsigned long long d;
    asm("add.rn.f32x2 %0, %1, %2;" : "=l"(d) : "l"(a), "l"(b));
    return d;
}

// ---------------------------------------------------------------- zero + cnt
// One kernel, grid EXACTLY 148 blocks (all co-resident -> spin sync is safe).
// Phase A: zero g_cnt/g_bpub. Device-wide handshake. Phase B: degree atomics.
__global__ __launch_bounds__(256) void zero_cnt_kernel(const int4* __restrict__ dst4,
                                                       int e, int n) {
    const int tid = blockIdx.x * blockDim.x + threadIdx.x;
    const int nthr = gridDim.x * blockDim.x;

    for (int i = tid; i < n; i += nthr) g_cnt[i] = 0;
    if (tid < 128) g_bpub[tid] = 0;

    __threadfence();
    __syncthreads();
    if (threadIdx.x == 0) {
        int arrived = atomicAdd(&g_sync, 1) + 1;
        if (arrived == (int)gridDim.x) atomicExch(&g_sync_release, 1);
        while (atomicAdd(&g_sync_release, 0) == 0) {}
    }
    __syncthreads();

    const int e4 = e >> 2;
    for (int i = tid; i < e4; i += nthr) {
        int4 d = dst4[i];
        atomicAdd(&g_cnt[d.x], 1);
        atomicAdd(&g_cnt[d.y], 1);
        atomicAdd(&g_cnt[d.z], 1);
        atomicAdd(&g_cnt[d.w], 1);
    }
    if (tid == 0) {
        const int* d1 = (const int*)dst4;
        for (int j = e4 * 4; j < e; j++) atomicAdd(&g_cnt[d1[j]], 1);
    }
}

// Single-pass exclusive scan (decoupled lookback; all blocks co-resident).
__global__ __launch_bounds__(1024) void scan_kernel(int n) {
    __shared__ int sh[1024];
    __shared__ int red[1024];
    const int t = threadIdx.x;
    const int b = blockIdx.x;
    const int i = b * 1024 + t;
    if (b == 0 && t == 0) { g_sync = 0; g_sync_release = 0; }  // reset handshake
    int v = (i < n) ? g_cnt[i] : 0;
    sh[t] = v;
    __syncthreads();
    #pragma unroll
    for (int d = 1; d < 1024; d <<= 1) {
        int u = (t >= d) ? sh[t - d] : 0;
        __syncthreads();
        sh[t] += u;
        __syncthreads();
    }
    int incl = sh[t];
    if (t == 1023) atomicExch(&g_bpub[b], incl | PUB_FLAG);

    int pv = 0;
    if (t < b) {
        int w;
        do { w = atomicAdd(&g_bpub[t], 0); } while ((w & PUB_FLAG) == 0);
        pv = w & (PUB_FLAG - 1);
    }
    red[t] = pv;
    __syncthreads();
    #pragma unroll
    for (int s = 512; s > 0; s >>= 1) {
        if (t < s) red[t] += red[t + s];
        __syncthreads();
    }
    int prefix = red[0];
    if (i < n) { g_off[i] = prefix + incl - v; g_pos[i] = 0; }
}

// ---------------------------------------------------------------- GEMM1 + fill
// Blocks [0, nGemm): hs[r][c] = fp16( rsqrt(cnt[r]+1) * sum_k x[r][k]*Wc[k][c] )
//   Tile M=128, N=64, K chunks of 32 (R8 synchronous structure — known good).
// Blocks [nGemm, ...): CSR fill, 4 edges/thread (overlaps with the GEMM).
__global__ __launch_bounds__(256) void gemm1_fill_kernel(const float* __restrict__ x,
                                                         const float* __restrict__ Wc,
                                                         const int* __restrict__ src,
                                                         const int* __restrict__ dst,
                                                         int n, int e, int nGemm) {
    __shared__ float4 Xs[128 * 9];
    __shared__ float4 Ws[32 * 16];

    if (blockIdx.x >= nGemm) {   // ---- fill part
        int i = (blockIdx.x - nGemm) * 256 + threadIdx.x;
        int e4 = e >> 2;
        if (i < e4) {
            int4 s4 = ((const int4*)src)[i];
            int4 d4 = ((const int4*)dst)[i];
            int p;
            p = g_off[d4.x] + atomicAdd(&g_pos[d4.x], 1); g_csr[p] = s4.x;
            p = g_off[d4.y] + atomicAdd(&g_pos[d4.y], 1); g_csr[p] = s4.y;
            p = g_off[d4.z] + atomicAdd(&g_pos[d4.z], 1); g_csr[p] = s4.z;
            p = g_off[d4.w] + atomicAdd(&g_pos[d4.w], 1); g_csr[p] = s4.w;
        }
        if (i == 0) {
            for (int j = e4 * 4; j < e; j++) {
                int d = dst[j];
                int p = g_off[d] + atomicAdd(&g_pos[d], 1);
                g_csr[p] = src[j];
            }
        }
        return;
    }

    const int t = threadIdx.x;
    const int rowBase = blockIdx.x * 128;
    const int tr = t & 31;
    const int tc = t >> 5;

    unsigned long long acc[4][4];
    #pragma unroll
    for (int i = 0; i < 4; i++)
        #pragma unroll
        for (int c2 = 0; c2 < 4; c2++) acc[i][c2] = 0ull;

    const float4* Xg = (const float4*)x;
    const float4* Wg = (const float4*)Wc;

    for (int c = 0; c < 4; c++) {
        #pragma unroll
        for (int i = 0; i < 2; i++) {
            int idx = t + i * 256;
            int k = idx >> 4, col4 = idx & 15;
            Ws[idx] = Wg[(c * 32 + k) * 16 + col4];
        }
        #pragma unroll
        for (int i = 0; i < 4; i++) {
            int idx = t + i * 256;
            int r = idx >> 3, q = idx & 7;
            int row = rowBase + r;
            float4 v = make_float4(0.f, 0.f, 0.f, 0.f);
            if (row < n) v = Xg[(size_t)row * 32 + c * 8 + q];
            Xs[r * 9 + q] = v;
        }
        __syncthreads();

        #pragma unroll
        for (int kq = 0; kq < 8; kq++) {
            float4 xv[4];
            #pragma unroll
            for (int i = 0; i < 4; i++) xv[i] = Xs[(tr + 32 * i) * 9 + kq];
            #pragma unroll
            for (int kk = 0; kk < 4; kk++) {
                float4 w0 = Ws[(kq * 4 + kk) * 16 + tc * 2];
                float4 w1 = Ws[(kq * 4 + kk) * 16 + tc * 2 + 1];
                unsigned long long wp0 = pack2(w0.x, w0.y);
                unsigned long long wp1 = pack2(w0.z, w0.w);
                unsigned long long wp2 = pack2(w1.x, w1.y);
                unsigned long long wp3 = pack2(w1.z, w1.w);
                #pragma unroll
                for (int i = 0; i < 4; i++) {
                    float s = (kk == 0) ? xv[i].x : (kk == 1) ? xv[i].y
                            : (kk == 2) ? xv[i].z : xv[i].w;
                    unsigned long long ss = pack2(s, s);
                    ffma2(acc[i][0], ss, wp0);
                    ffma2(acc[i][1], ss, wp1);
                    ffma2(acc[i][2], ss, wp2);
                    ffma2(acc[i][3], ss, wp3);
                }
            }
        }
        __syncthreads();
    }

    #pragma unroll
    for (int i = 0; i < 4; i++) {
        int row = rowBase + tr + 32 * i;
        if (row < n) {
            float dv = rsqrtf((float)g_cnt[row] + 1.0f);
            unsigned long long dd = pack2(dv, dv);
            float2 a = unpack2(mul2(acc[i][0], dd));
            float2 b = unpack2(mul2(acc[i][1], dd));
            float2 cc = unpack2(mul2(acc[i][2], dd));
            float2 d = unpack2(mul2(acc[i][3], dd));
            __half2 h0 = __floats2half2_rn(a.x, a.y);
            __half2 h1 = __floats2half2_rn(b.x, b.y);
            __half2 h2 = __floats2half2_rn(cc.x, cc.y);
            __half2 h3 = __floats2half2_rn(d.x, d.y);
            uint4 pk;
            pk.x = *(unsigned int*)&h0;
            pk.y = *(unsigned int*)&h1;
            pk.z = *(unsigned int*)&h2;
            pk.w = *(unsigned int*)&h3;
            ((uint4*)g_hs)[(size_t)row * 8 + tc] = pk;
        }
    }
}

// ---------------------------------------------------------------- agg + GEMM2
// Block handles 64 rows. Phase 1: 8 threads/node (uint4 = 8 halves each),
// 32 nodes per pass, 2 passes; fp32 accumulate; dinv/bias/relu -> Hs.
// Phase 2: out = Hs@Wlin + blin (f32x2).
__global__ __launch_bounds__(256) void agg_gemm2_kernel(const float* __restrict__ Wlin,
                                                        const float* __restrict__ bconv,
                                                        const float* __restrict__ blin,
                                                        float* __restrict__ out,
                                                        int n) {
    __shared__ float4 Hs[64 * 17];   // 64 rows x 16 float4 (+1 pad)
    __shared__ float4 Ws[32 * 32];   // 32 k x 128 cols
    const int t = threadIdx.x;
    const int rowBase = blockIdx.x * 64;
    const int tr = t & 31;
    const int tc = t >> 5;

    // ---- phase 1: aggregate (fp16 gather, fp32 accumulate, 4-deep unroll)
    {
        const int grp = t >> 3;      // 0..31 (node within pass)
        const int c8 = t & 7;        // uint4 chunk: floats [c8*8, c8*8+8)
        const uint4* hs4 = (const uint4*)g_hs;
        float4 bcv0 = __ldg((const float4*)&bconv[c8 * 8]);
        float4 bcv1 = __ldg((const float4*)&bconv[c8 * 8 + 4]);
        #pragma unroll
        for (int pass = 0; pass < 2; pass++) {
            int r = pass * 32 + grp;
            int node = rowBase + r;
            float4 r0 = make_float4(0.f, 0.f, 0.f, 0.f);
            float4 r1 = make_float4(0.f, 0.f, 0.f, 0.f);
            if (node < n) {
                float a[8] = {0,0,0,0,0,0,0,0};
                float b[8] = {0,0,0,0,0,0,0,0};
                {   // self-loop
                    uint4 v = hs4[(size_t)node * 8 + c8];
                    const __half2* hp = (const __half2*)&v;
                    #pragma unroll
                    for (int m = 0; m < 4; m++) {
                        float2 f = __half22float2(hp[m]);
                        a[m * 2] += f.x; a[m * 2 + 1] += f.y;
                    }
                }
                int cnt = g_cnt[node];
                int beg = g_off[node];
                int end = beg + cnt;
                int j = beg;
                for (; j + 3 < end; j += 4) {
                    int s0 = g_csr[j],     s1 = g_csr[j + 1];
                    int s2 = g_csr[j + 2], s3 = g_csr[j + 3];
                    uint4 v0 = hs4[(size_t)s0 * 8 + c8];
                    uint4 v1 = hs4[(size_t)s1 * 8 + c8];
                    uint4 v2 = hs4[(size_t)s2 * 8 + c8];
                    uint4 v3 = hs4[(size_t)s3 * 8 + c8];
                    const __half2* h0 = (const __half2*)&v0;
                    const __half2* h1 = (const __half2*)&v1;
                    const __half2* h2 = (const __half2*)&v2;
                    const __half2* h3 = (const __half2*)&v3;
                    #pragma unroll
                    for (int m = 0; m < 4; m++) {
                        float2 f0 = __half22float2(h0[m]);
                        float2 f1 = __half22float2(h1[m]);
                        float2 f2 = __half22float2(h2[m]);
                        float2 f3 = __half22float2(h3[m]);
                        a[m * 2] += f0.x + f2.x; a[m * 2 + 1] += f0.y + f2.y;
                        b[m * 2] += f1.x + f3.x; b[m * 2 + 1] += f1.y + f3.y;
                    }
                }
                for (; j < end; j++) {
                    int s0 = g_csr[j];
                    uint4 v0 = hs4[(size_t)s0 * 8 + c8];
                    const __half2* h0 = (const __half2*)&v0;
                    #pragma unroll
                    for (int m = 0; m < 4; m++) {
                        float2 f0 = __half22float2(h0[m]);
                        a[m * 2] += f0.x; a[m * 2 + 1] += f0.y;
                    }
                }
                float dv = rsqrtf((float)cnt + 1.0f);
                r0.x = fmaxf(fmaf(a[0] + b[0], dv, bcv0.x), 0.f);
                r0.y = fmaxf(fmaf(a[1] + b[1], dv, bcv0.y), 0.f);
                r0.z = fmaxf(fmaf(a[2] + b[2], dv, bcv0.z), 0.f);
                r0.w = fmaxf(fmaf(a[3] + b[3], dv, bcv0.w), 0.f);
                r1.x = fmaxf(fmaf(a[4] + b[4], dv, bcv1.x), 0.f);
                r1.y = fmaxf(fmaf(a[5] + b[5], dv, bcv1.y), 0.f);
                r1.z = fmaxf(fmaf(a[6] + b[6], dv, bcv1.z), 0.f);
                r1.w = fmaxf(fmaf(a[7] + b[7], dv, bcv1.w), 0.f);
            }
            Hs[r * 17 + c8 * 2]     = r0;
            Hs[r * 17 + c8 * 2 + 1] = r1;
        }
    }

    // ---- phase 2: GEMM, K=64 in 2 chunks of 32 (Ws reuse)
    unsigned long long acc[2][8];
    #pragma unroll
    for (int i = 0; i < 2; i++)
        #pragma unroll
        for (int c2 = 0; c2 < 8; c2++) acc[i][c2] = 0ull;

    const float4* Wg = (const float4*)Wlin;

    for (int c = 0; c < 2; c++) {
        __syncthreads();   // Hs ready (c==0) / Ws drained (c==1)
        #pragma unroll
        for (int i = 0; i < 4; i++) {
            int idx = t + i * 256;
            int k = idx >> 5, col4 = idx & 31;
            Ws[idx] = Wg[(c * 32 + k) * 32 + col4];
        }
        __syncthreads();

        #pragma unroll
        for (int kq = 0; kq < 8; kq++) {
            float4 xv[2];
            #pragma unroll
            for (int i = 0; i < 2; i++) xv[i] = Hs[(tr + 32 * i) * 17 + c * 8 + kq];
            #pragma unroll
            for (int kk = 0; kk < 4; kk++) {
                unsigned long long wp[8];
                #pragma unroll
                for (int m = 0; m < 4; m++) {
                    float4 w = Ws[(kq * 4 + kk) * 32 + tc * 4 + m];
                    wp[m * 2]     = pack2(w.x, w.y);
                    wp[m * 2 + 1] = pack2(w.z, w.w);
                }
                #pragma unroll
                for (int i = 0; i < 2; i++) {
                    float s = (kk == 0) ? xv[i].x : (kk == 1) ? xv[i].y
                            : (kk == 2) ? xv[i].z : xv[i].w;
                    unsigned long long ss = pack2(s, s);
                    #pragma unroll
                    for (int c2 = 0; c2 < 8; c2++) ffma2(acc[i][c2], ss, wp[c2]);
                }
            }
        }
    }

    unsigned long long blp[8];
    #pragma unroll
    for (int m = 0; m < 4; m++) {
        float4 b = __ldg((const float4*)&blin[tc * 16 + m * 4]);
        blp[m * 2]     = pack2(b.x, b.y);
        blp[m * 2 + 1] = pack2(b.z, b.w);
    }
    #pragma unroll
    for (int i = 0; i < 2; i++) {
        int row = rowBase + tr + 32 * i;
        if (row < n) {
            size_t off = (size_t)row * 32 + tc * 4;
            #pragma unroll
            for (int m = 0; m < 4; m++) {
                float2 lo = unpack2(add2(acc[i][m * 2],     blp[m * 2]));
                float2 hi = unpack2(add2(acc[i][m * 2 + 1], blp[m * 2 + 1]));
                ((float4*)out)[off + m] = make_float4(lo.x, lo.y, hi.x, hi.y);
            }
        }
    }
}

// ---------------------------------------------------------------- launch
extern "C" void kernel_launch(void* const* d_in, const int* in_sizes, int n_in,
                              void* d_out, int out_size) {
    const float* x  = (const float*)d_in[0];
    const int*   ei = (const int*)  d_in[1];
    const float* Wc = (const float*)d_in[2];
    const float* bc = (const float*)d_in[3];
    const float* Wl = (const float*)d_in[4];
    const float* bl = (const float*)d_in[5];
    float*       out = (float*)d_out;

    const int n = in_sizes[0] / IN_DIM;      // 100000
    const int e = in_sizes[1] / 2;           // 1600000
    const int* src = ei;
    const int* dst = ei + e;
    const int nb = (n + 1023) >> 10;         // 98 (must be <= 128)

    zero_cnt_kernel<<<148, 256>>>((const int4*)dst, e, n);
    scan_kernel<<<nb, 1024>>>(n);
    {
        int nGemm = (n + 127) / 128;
        int nFill = ((e >> 2) + 255) / 256;
        gemm1_fill_kernel<<<nGemm + nFill, 256>>>(x, Wc, src, dst, n, e, nGemm);
    }
    agg_gemm2_kernel<<<(n + 63) / 64, 256>>>(Wl, bc, bl, out, n);
}